// round 14
// baseline (speedup 1.0000x reference)
#include <cuda_runtime.h>
#include <cstdint>

// upfirdn2d, UP=1, DOWN=2, PAD=5, separable sym6 (12 taps), fp32.
// cp.async pipeline, 3-way warp specialization:
//   warps 0-7  (256 thr): vertical 12-tap (chunk c) ring -> tmp[c&1]
//   warps 8-11 (128 thr): horizontal 12-tap (chunk c-1), 8 outputs/thread
//   warps 12-15(128 thr): cp.async issue + wait (4 x 16B per load chunk)
// Chunk loop fully unrolled: ring wrap / buffer parity are constants.

#define IMG_H   256
#define IMG_W   256
#define OUT_H   128
#define OUT_W   128
#define NT      512
#define NCH     8             // compute chunks (8 out rows each)
#define NLC     18            // 8-input-row load chunks
#define RROWS   48            // ring rows (6 slots x 8)
#define RSTRIDE 256
#define TSTRIDE 276           // 276 % 32 = 20
#define PADL    8
#define TBUF    (8 * TSTRIDE)

#define HR0  ( 0.015404109327027373f)
#define HR1  ( 0.0034907120842174702f)
#define HR2  (-0.11799011114819057f)
#define HR3  (-0.048311742585633f)
#define HR4  ( 0.4910559419267466f)
#define HR5  ( 0.787641141030194f)
#define HR6  ( 0.3379294217276218f)
#define HR7  (-0.07263752278646252f)
#define HR8  (-0.021060292512300564f)
#define HR9  ( 0.04472490177066578f)
#define HR10 ( 0.0017677118642428036f)
#define HR11 (-0.007800708325034148f)

__device__ __forceinline__ float tap12(const float* w) {
    float a;
    a = HR0 * w[0];
    a = fmaf(HR1,  w[1],  a);
    a = fmaf(HR2,  w[2],  a);
    a = fmaf(HR3,  w[3],  a);
    a = fmaf(HR4,  w[4],  a);
    a = fmaf(HR5,  w[5],  a);
    a = fmaf(HR6,  w[6],  a);
    a = fmaf(HR7,  w[7],  a);
    a = fmaf(HR8,  w[8],  a);
    a = fmaf(HR9,  w[9],  a);
    a = fmaf(HR10, w[10], a);
    a = fmaf(HR11, w[11], a);
    return a;
}

__device__ __forceinline__ void cp_async16(uint32_t saddr, const void* gptr) {
    asm volatile("cp.async.cg.shared.global [%0], [%1], 16;\n"
                 :: "r"(saddr), "l"(gptr));
}
__device__ __forceinline__ void cp_commit() {
    asm volatile("cp.async.commit_group;\n" ::: "memory");
}
template<int N>
__device__ __forceinline__ void cp_wait() {
    asm volatile("cp.async.wait_group %0;\n" :: "n"(N) : "memory");
}

// H: 8 outputs (cols 8g..8g+7 of one row) from a 32-word window.
// rowv = tmp row + 16g words; out d reads rowv[2d+3 .. 2d+14].
// Two-phase: 24 words -> d0..3, then 8 more -> d4..7 (caps live regs).
__device__ __forceinline__ void hoct(const float* __restrict__ rowv,
                                     float* __restrict__ dst)
{
    float v[32];
    #pragma unroll
    for (int m = 0; m < 6; m++) {
        float4 q = *reinterpret_cast<const float4*>(rowv + 4 * m);
        v[4*m+0] = q.x; v[4*m+1] = q.y; v[4*m+2] = q.z; v[4*m+3] = q.w;
    }
    float4 o;
    o.x = tap12(&v[3]);
    o.y = tap12(&v[5]);
    o.z = tap12(&v[7]);
    o.w = tap12(&v[9]);
    *reinterpret_cast<float4*>(dst) = o;

    #pragma unroll
    for (int m = 6; m < 8; m++) {
        float4 q = *reinterpret_cast<const float4*>(rowv + 4 * m);
        v[4*m+0] = q.x; v[4*m+1] = q.y; v[4*m+2] = q.z; v[4*m+3] = q.w;
    }
    o.x = tap12(&v[11]);
    o.y = tap12(&v[13]);
    o.z = tap12(&v[15]);
    o.w = tap12(&v[17]);
    *reinterpret_cast<float4*>(dst + 4) = o;
}

__global__ void __launch_bounds__(NT, 3)
hp_sym6_v12(const float* __restrict__ in, float* __restrict__ out)
{
    extern __shared__ float smem_[];
    float* s_ring = smem_;                        // 48 * 256  (49152 B)
    float* s_tmp  = smem_ + RROWS * RSTRIDE;      // 2 * 8 * 276 (17664 B)

    const int ty  = blockIdx.x;
    const int img = blockIdx.y;
    const int tid = threadIdx.x;
    const int i0  = ty * 64;
    const int g0  = 2 * i0 - 5;

    const float* __restrict__ src    = in  + (size_t)img * (IMG_H * IMG_W);
    float*       __restrict__ dstimg = out + (size_t)img * (OUT_H * OUT_W);

    // zero tmp pad words [0,8) and [264,276) of both buffers
    for (int z = tid; z < 2 * 8 * 20; z += NT) {
        int b  = z / 160;
        int zz = z - b * 160;
        int rr = zz / 20;
        int pz = zz - rr * 20;
        s_tmp[b * TBUF + rr * TSTRIDE + (pz < 8 ? pz : 256 + pz)] = 0.0f;
    }

    const bool is_v    = (tid < 256);
    const bool is_h    = (tid >= 256 && tid < 384);
    const bool is_load = (tid >= 384);

    // loader mapping: 128 threads, 4 x 16B each per 8-row load chunk
    const int ltid = tid - 384;

    auto issue_load = [&](int L) {
        if (L < NLC) {
            #pragma unroll
            for (int k = 0; k < 4; k++) {
                int idx = ltid + 128 * k;          // float4 index in 8x256 chunk
                int r   = idx >> 6;                // 0..7
                int c4  = idx & 63;
                int rel  = 8 * L + r;
                int srow = (L % 6) * 8 + r;
                float* sp = s_ring + srow * RSTRIDE + c4 * 4;
                int g = g0 + rel;
                if ((unsigned)g < (unsigned)IMG_H) {
                    cp_async16((uint32_t)__cvta_generic_to_shared(sp),
                               reinterpret_cast<const float4*>(src + g * IMG_W) + c4);
                } else {
                    *reinterpret_cast<float4*>(sp) = make_float4(0.f, 0.f, 0.f, 0.f);
                }
            }
        }
        cp_commit();
    };

    if (is_load) {
        issue_load(0); issue_load(1); issue_load(2);
        issue_load(3); issue_load(4); issue_load(5);
    }

    // V mapping: one column, 8 outputs per chunk, 26 front-batched LDS
    const int vcol = tid & 255;
    // H mapping: 128 threads -> (row 0..7, group 0..15 of 8 cols)
    const int htid = tid - 256;
    const int hrow = htid >> 4;
    const int hg   = htid & 15;

    #pragma unroll
    for (int c = 0; c < NCH; c++) {
        if (is_load) cp_wait<2>();     // load chunks <= 2c+3 complete
        __syncthreads();               // ring visible CTA-wide; prev H done

        if (is_v) {
            const int rbase = (c % 3) * 16;        // constant (loop unrolled)
            float w[26];
            #pragma unroll
            for (int t = 0; t < 26; t++) {
                int r = rbase + t;  if (r >= RROWS) r -= RROWS;   // constant
                w[t] = s_ring[r * RSTRIDE + vcol];
            }
            float* tdst = s_tmp + (c & 1) * TBUF + PADL + vcol;
            #pragma unroll
            for (int m = 0; m < 8; m++)
                tdst[m * TSTRIDE] = tap12(&w[2 * m]);
        } else if (is_h && c > 0) {
            const float* rowv = s_tmp + ((c - 1) & 1) * TBUF
                              + hrow * TSTRIDE + 16 * hg;
            hoct(rowv, dstimg + (i0 + 8 * (c - 1) + hrow) * OUT_W + 8 * hg);
        }
        __syncthreads();
        if (is_load) { issue_load(2 * c + 6); issue_load(2 * c + 7); }
    }

    // final H for chunk NCH-1 (ordered by the loop's last barrier)
    if (is_h) {
        const float* rowv = s_tmp + ((NCH - 1) & 1) * TBUF
                          + hrow * TSTRIDE + 16 * hg;
        hoct(rowv, dstimg + (i0 + 8 * (NCH - 1) + hrow) * OUT_W + 8 * hg);
    }
}

extern "C" void kernel_launch(void* const* d_in, const int* in_sizes, int n_in,
                              void* d_out, int out_size)
{
    const float* x = (const float*)d_in[0];
    float* y = (float*)d_out;

    int n_img = in_sizes[0] / (IMG_H * IMG_W);                        // 1024
    size_t smem = (size_t)(RROWS * RSTRIDE + 2 * TBUF) * sizeof(float); // 66816 B

    cudaFuncSetAttribute(hp_sym6_v12,
                         cudaFuncAttributeMaxDynamicSharedMemorySize, (int)smem);

    dim3 grid(OUT_H / 64, n_img);   // (2, 1024)
    hp_sym6_v12<<<grid, NT, smem>>>(x, y);
}

// round 15
// speedup vs baseline: 1.0081x; 1.0081x over previous
#include <cuda_runtime.h>
#include <cstdint>

// upfirdn2d, UP=1, DOWN=2, PAD=5, separable sym6 (12 taps), fp32.
// v13: v3 dataflow (input -> registers via LDG, tmp in smem) chunked into
// 4 x 16 output rows, with prefetch.global.L2 of chunk c+1's input issued
// during H(c). V(c>=1) then hits L2 (~half latency) -> higher sustained BW,
// and DRAM stays busy through the H phases.

#define IMG_H   256
#define IMG_W   256
#define OUT_H   128
#define OUT_W   128
#define NT      512
#define NCHK    4             // chunks per CTA (16 out rows each)
#define TSTRIDE 276           // 276 % 32 = 20
#define PADL    8             // data words [8, 264)

#define HR0  ( 0.015404109327027373f)
#define HR1  ( 0.0034907120842174702f)
#define HR2  (-0.11799011114819057f)
#define HR3  (-0.048311742585633f)
#define HR4  ( 0.4910559419267466f)
#define HR5  ( 0.787641141030194f)
#define HR6  ( 0.3379294217276218f)
#define HR7  (-0.07263752278646252f)
#define HR8  (-0.021060292512300564f)
#define HR9  ( 0.04472490177066578f)
#define HR10 ( 0.0017677118642428036f)
#define HR11 (-0.007800708325034148f)

__device__ __forceinline__ float tap12(const float* w) {
    float a;
    a = HR0 * w[0];
    a = fmaf(HR1,  w[1],  a);
    a = fmaf(HR2,  w[2],  a);
    a = fmaf(HR3,  w[3],  a);
    a = fmaf(HR4,  w[4],  a);
    a = fmaf(HR5,  w[5],  a);
    a = fmaf(HR6,  w[6],  a);
    a = fmaf(HR7,  w[7],  a);
    a = fmaf(HR8,  w[8],  a);
    a = fmaf(HR9,  w[9],  a);
    a = fmaf(HR10, w[10], a);
    a = fmaf(HR11, w[11], a);
    return a;
}

__device__ __forceinline__ void pf_l2(const void* p) {
    asm volatile("prefetch.global.L2 [%0];" :: "l"(p));
}

// Vertical: 8 output rows of ONE column; 26 front-batched coalesced LDG.32.
template<bool CHECK>
__device__ __forceinline__ void vstrip8(const float* __restrict__ colp,
                                        float* __restrict__ sdst, int g0)
{
    float w[26];
    #pragma unroll
    for (int t = 0; t < 26; t++) {
        int g = g0 + t;
        if (CHECK && (unsigned)g >= (unsigned)IMG_H) w[t] = 0.0f;
        else                                         w[t] = __ldg(colp + g * IMG_W);
    }
    #pragma unroll
    for (int m = 0; m < 8; m++)
        sdst[m * TSTRIDE] = tap12(&w[2 * m]);
}

// Horizontal: 4 outputs (cols 4g..4g+3) from a 24-word window (v11-proven).
__device__ __forceinline__ void hquad(const float* __restrict__ rowv,
                                      float* __restrict__ dst)
{
    float v[24];
    #pragma unroll
    for (int m = 0; m < 6; m++) {
        float4 q = *reinterpret_cast<const float4*>(rowv + 4 * m);
        v[4*m+0] = q.x; v[4*m+1] = q.y; v[4*m+2] = q.z; v[4*m+3] = q.w;
    }
    float4 o;
    o.x = tap12(&v[3]);
    o.y = tap12(&v[5]);
    o.z = tap12(&v[7]);
    o.w = tap12(&v[9]);
    *reinterpret_cast<float4*>(dst) = o;
}

__global__ void __launch_bounds__(NT, 2)
hp_sym6_v13(const float* __restrict__ in, float* __restrict__ out)
{
    __shared__ float s_tmp[16 * TSTRIDE];     // 17664 B

    const int ty  = blockIdx.x;               // tile (fastest -> L2 halo reuse)
    const int img = blockIdx.y;
    const int tid = threadIdx.x;
    const int i0  = ty * 64;                  // first output row of tile

    const float* __restrict__ src    = in  + (size_t)img * (IMG_H * IMG_W);
    float*       __restrict__ dstimg = out + (size_t)img * (OUT_H * OUT_W);

    // warm L2 for chunk 0's window: rows [2*i0-5, 2*i0+36] (42 rows x 8 lines)
    {
        int r = tid >> 3;                     // 0..63
        if (r < 42) {
            int g = 2 * i0 - 5 + r;
            if ((unsigned)g < (unsigned)IMG_H)
                pf_l2(src + g * IMG_W + (tid & 7) * 32);
        }
    }

    // zero tmp pad words [0,8) and [264,276) per row
    for (int z = tid; z < 16 * 20; z += NT) {
        int rr = z / 20;
        int pz = z - rr * 20;
        s_tmp[rr * TSTRIDE + (pz < 8 ? pz : 256 + pz)] = 0.0f;
    }

    // V mapping: (column, half): half h -> chunk rows 8h..8h+7
    const int vcol = tid & 255;
    const int vh   = tid >> 8;
    const float* colp = src + vcol;

    // H mapping: (row in chunk, group of 4 output cols)
    const int hrow = tid >> 5;                // 0..15
    const int hg   = tid & 31;                // cols 4*hg .. 4*hg+3

    #pragma unroll 1
    for (int c = 0; c < NCHK; c++) {
        // ---- V(c): 16 out rows from global (L2-hot for c>=1) ----
        {
            const int g0 = 2 * (i0 + 16 * c + 8 * vh) - 5;   // 26-row window
            float* sdst = &s_tmp[(8 * vh) * TSTRIDE + PADL + vcol];
            if (g0 >= 0 && g0 + 25 < IMG_H) vstrip8<false>(colp, sdst, g0);
            else                            vstrip8<true >(colp, sdst, g0);
        }
        __syncthreads();

        // ---- prefetch chunk c+1's 32 new input rows into L2 ----
        if (c < NCHK - 1 && tid < 256) {
            int g = 2 * i0 + 32 * c + 37 + (tid >> 3);       // 32 rows
            if ((unsigned)g < (unsigned)IMG_H)
                pf_l2(src + g * IMG_W + (tid & 7) * 32);
        }

        // ---- H(c): 4 outputs/thread from tmp ----
        {
            const float* rowv = s_tmp + hrow * TSTRIDE + 8 * hg;
            hquad(rowv, dstimg + (i0 + 16 * c + hrow) * OUT_W + 4 * hg);
        }
        __syncthreads();   // H reads done before next V overwrites tmp
    }
}

extern "C" void kernel_launch(void* const* d_in, const int* in_sizes, int n_in,
                              void* d_out, int out_size)
{
    const float* x = (const float*)d_in[0];
    float* y = (float*)d_out;

    int n_img = in_sizes[0] / (IMG_H * IMG_W);   // 1024
    dim3 grid(OUT_H / 64, n_img);                // (2, 1024)
    hp_sym6_v13<<<grid, NT>>>(x, y);
}